// round 15
// baseline (speedup 1.0000x reference)
#include <cuda_runtime.h>
#include <cuda_bf16.h>
#include <cstdint>
#include <math.h>

// ---------------- problem constants ----------------
#define TD      50000
#define E_NO    2000
#define I_NO    500
#define CCH     63
#define TN      200
#define OBS_LEN 401
#define NB      13
#define PI_F    3.14159265358979323846f
#define TT      2048
#define NTILE   25
#define TDP     (NTILE * TT)               // 51200 (zf stride)
#define EFTILE  4096
#define EFNT    13                         // ceil(50000/4096)
#define EFP     (EFNT * EFTILE)            // 53248 (ef stride)

// ---------------- device scratch ----------------
__device__ float g_ek[CCH * TN];
__device__ float g_ik[CCH * TN];
__device__ float g_ok[CCH * (OBS_LEN + 3)];
__device__ float g_syn_e[CCH * TD];        // CENTERED syn_e
__device__ float g_syn_i[CCH * TD];        // CENTERED syn_i
__device__ float g_zf[CCH * TDP];          // obs result
__device__ float g_ef[CCH * EFP];          // e+i conv result (uncorrected)
__device__ float g_se[CCH];                // bf16-exact shift for syn_e
__device__ float g_si[CCH];
__device__ float g_corr[CCH];              // s_e*sum(ek) + s_i*sum(ik)

// pack two fp32 -> bf16x2 (lo = first/even, hi = second/odd)
__device__ __forceinline__ uint32_t bf2(float lo, float hi) {
    uint32_t r;
    asm("cvt.rn.bf16x2.f32 %0, %1, %2;" : "=r"(r) : "f"(hi), "f"(lo));
    return r;
}

// ============================================================
// Kernel 0: build temporal kernels (601 blocks, fp32 MUFU basis)
// ============================================================
__global__ __launch_bounds__(64) void build_kernels_kernel(
    const float* __restrict__ W_syn, const float* __restrict__ W_obs)
{
    __shared__ float bs[NB];
    const int blk = blockIdx.x;
    const int tid = threadIdx.x;

    if (blk < TN) {
        const int j = blk;
        if (tid < NB) {
            float raw = 5.f * logf((float)j + 1.f + 1e-8f);
            float phi = 0.5f * PI_F * (float)tid;
            float v = 0.5f * cosf(raw - phi) + 0.5f;
            if (raw < phi - PI_F || raw > phi + PI_F) v = 0.f;
            bs[tid] = v;
        }
        __syncthreads();
        if (tid < CCH) {
            const int c = tid;
            float ae = 0.f, ai = 0.f;
            #pragma unroll
            for (int b = 0; b < NB; b++) {
                ae = fmaf(W_syn[(c * NB + b) * 2 + 0], bs[b], ae);
                ai = fmaf(W_syn[(c * NB + b) * 2 + 1], bs[b], ai);
            }
            g_ek[c * TN + j] = ae;
            g_ik[c * TN + j] = ai;
        }
    } else {
        const int j = blk - TN;
        if (tid < NB) {
            float xo = (float)(j - TN);
            float raw = 5.f * logf(fabsf(xo) + 1.f + 1e-8f);
            float phi = 0.5f * PI_F * (float)tid;
            float v = 0.5f * cosf(raw - phi) + 0.5f;
            if (raw < phi - PI_F || raw > phi + PI_F) v = 0.f;
            bs[tid] = v;
        }
        __syncthreads();
        if (tid < CCH) {
            const int c = tid;
            float a = W_obs[c * 25 + 0] * bs[0];
            #pragma unroll
            for (int b = 1; b < NB; b++) {
                if (j >= TN) a = fmaf(W_obs[c * 25 + 2 * b - 1], bs[b], a);
                if (j <= TN) a = fmaf(W_obs[c * 25 + 2 * b    ], bs[b], a);
            }
            g_ok[c * (OBS_LEN + 3) + j] = a;
        }
    }
}

// ============================================================
// Kernel 0b: per-channel shifts s (bf16-exact) + correction consts
// ============================================================
__global__ __launch_bounds__(256) void aux_kernel(
    const float* __restrict__ C_se, const float* __restrict__ C_si)
{
    __shared__ float red[256];
    const int c   = blockIdx.x;
    const int tid = threadIdx.x;

    float se = 0.f, si = 0.f, ke = 0.f, ki = 0.f;
    for (int k = tid; k < E_NO; k += 256) se += C_se[(size_t)(c + 1) * E_NO + k];
    for (int k = tid; k < I_NO; k += 256) si += C_si[(size_t)(c + 1) * I_NO + k];
    for (int j = tid; j < TN; j += 256) { ke += g_ek[c * TN + j]; ki += g_ik[c * TN + j]; }

    float vals[4] = {se, si, ke, ki};
    float outv[4];
    for (int q = 0; q < 4; q++) {
        red[tid] = vals[q];
        __syncthreads();
        for (int s = 128; s > 0; s >>= 1) {
            if (tid < s) red[tid] += red[tid + s];
            __syncthreads();
        }
        outv[q] = red[0];
        __syncthreads();
    }
    if (tid == 0) {
        float s_e = __bfloat162float(__float2bfloat16(0.5f * outv[0]));
        float s_i = __bfloat162float(__float2bfloat16(0.5f * outv[1]));
        g_se[c] = s_e;
        g_si[c] = s_i;
        g_corr[c] = s_e * outv[2] + s_i * outv[3];
    }
}

// ============================================================
// Kernel 1: bf16 mma.sync GEMM (verified config; epilogue centers)
// ============================================================
#define GBM     128
#define GBK     32
#define APW     20
#define AW      (128 * APW)
#define BW      (64 * APW)
#define STW     (AW + BW)
#define GSMEM_BYTES (64 * 132 * 4)
#define GEMM_GX 391

__global__ __launch_bounds__(256) void gemm_bf16_kernel(
    const float* __restrict__ Ae, const float* __restrict__ Cse, float* __restrict__ oute,
    const float* __restrict__ Ai, const float* __restrict__ Csi, float* __restrict__ outi)
{
    extern __shared__ float smf[];
    uint32_t* smw = reinterpret_cast<uint32_t*>(smf);

    const float* A; const float* Cs; float* outT; int K; const float* sarr;
    if (blockIdx.y == 0) { A = Ae; Cs = Cse; outT = oute; K = E_NO; sarr = g_se; }
    else                 { A = Ai; Cs = Csi; outT = outi; K = I_NO; sarr = g_si; }
    const int S = (K + GBK - 1) / GBK;

    const int tid  = threadIdx.x;
    const int wid  = tid >> 5;
    const int lane = tid & 31;
    const int g    = lane >> 2;
    const int t4   = lane & 3;
    const int wm   = (wid & 3) * 32;
    const int wn   = (wid >> 2) * 32;
    const int bm   = blockIdx.x * GBM;

    float acc[2][4][4];
    #pragma unroll
    for (int mi = 0; mi < 2; mi++)
        #pragma unroll
        for (int ni = 0; ni < 4; ni++)
            #pragma unroll
            for (int r = 0; r < 4; r++) acc[mi][ni][r] = 0.f;

    float4 ra[4], rb[2];

    auto ldg_stage = [&](int s) {
        const int k0 = s * GBK;
        #pragma unroll
        for (int j = 0; j < 4; j++) {
            int idx = tid + 256 * j, r = idx >> 3, q = idx & 7, k = k0 + q * 4;
            float4 v = make_float4(0.f, 0.f, 0.f, 0.f);
            if ((bm + r < TD) && (k + 4 <= K))
                v = *reinterpret_cast<const float4*>(A + (size_t)(bm + r) * K + k);
            ra[j] = v;
        }
        #pragma unroll
        for (int j = 0; j < 2; j++) {
            int idx = tid + 256 * j, r = idx >> 3, q = idx & 7, k = k0 + q * 4;
            float4 v = make_float4(0.f, 0.f, 0.f, 0.f);
            if ((r < CCH) && (k + 4 <= K))
                v = *reinterpret_cast<const float4*>(Cs + (size_t)(r + 1) * K + k);
            rb[j] = v;
        }
    };
    auto sts_stage = [&](int buf) {
        uint32_t* ab = smw + buf * STW;
        uint32_t* bb = ab + AW;
        #pragma unroll
        for (int j = 0; j < 4; j++) {
            int idx = tid + 256 * j, r = idx >> 3, q = idx & 7;
            uint2* p = reinterpret_cast<uint2*>(ab + r * APW + q * 2);
            *p = make_uint2(bf2(ra[j].x, ra[j].y), bf2(ra[j].z, ra[j].w));
        }
        #pragma unroll
        for (int j = 0; j < 2; j++) {
            int idx = tid + 256 * j, r = idx >> 3, q = idx & 7;
            uint2* p = reinterpret_cast<uint2*>(bb + r * APW + q * 2);
            *p = make_uint2(bf2(rb[j].x, rb[j].y), bf2(rb[j].z, rb[j].w));
        }
    };
    auto compute = [&](int buf) {
        const uint32_t* As = smw + buf * STW;
        const uint32_t* Bs = As + AW;
        #pragma unroll
        for (int ks = 0; ks < 2; ks++) {
            const int kw = ks * 8;
            uint32_t af[2][4];
            #pragma unroll
            for (int mi = 0; mi < 2; mi++) {
                int r = wm + mi * 16 + g;
                af[mi][0] = As[(r)     * APW + kw + t4];
                af[mi][1] = As[(r + 8) * APW + kw + t4];
                af[mi][2] = As[(r)     * APW + kw + 4 + t4];
                af[mi][3] = As[(r + 8) * APW + kw + 4 + t4];
            }
            uint32_t bf[4][2];
            #pragma unroll
            for (int ni = 0; ni < 4; ni++) {
                int n = wn + ni * 8 + g;
                bf[ni][0] = Bs[n * APW + kw + t4];
                bf[ni][1] = Bs[n * APW + kw + 4 + t4];
            }
            #pragma unroll
            for (int mi = 0; mi < 2; mi++)
                #pragma unroll
                for (int ni = 0; ni < 4; ni++) {
                    asm volatile(
                        "mma.sync.aligned.m16n8k16.row.col.f32.bf16.bf16.f32 "
                        "{%0,%1,%2,%3}, {%4,%5,%6,%7}, {%8,%9}, {%0,%1,%2,%3};"
                        : "+f"(acc[mi][ni][0]), "+f"(acc[mi][ni][1]),
                          "+f"(acc[mi][ni][2]), "+f"(acc[mi][ni][3])
                        : "r"(af[mi][0]), "r"(af[mi][1]), "r"(af[mi][2]), "r"(af[mi][3]),
                          "r"(bf[ni][0]), "r"(bf[ni][1]));
                }
        }
    };

    ldg_stage(0);
    sts_stage(0);
    __syncthreads();

    for (int s = 0; s < S; s++) {
        const bool have_next = (s + 1 < S);
        if (have_next) ldg_stage(s + 1);
        compute(s & 1);
        __syncthreads();
        if (have_next) {
            sts_stage((s + 1) & 1);
            __syncthreads();
        }
    }

    #pragma unroll
    for (int mi = 0; mi < 2; mi++)
        #pragma unroll
        for (int ni = 0; ni < 4; ni++) {
            int n0 = wn + ni * 8 + 2 * t4;
            int m0 = wm + mi * 16 + g;
            smf[(n0)     * 132 + m0]     = acc[mi][ni][0];
            smf[(n0 + 1) * 132 + m0]     = acc[mi][ni][1];
            smf[(n0)     * 132 + m0 + 8] = acc[mi][ni][2];
            smf[(n0 + 1) * 132 + m0 + 8] = acc[mi][ni][3];
        }
    __syncthreads();
    for (int idx = tid; idx < 64 * 128; idx += 256) {
        int c  = idx >> 7;
        int tl = idx & 127;
        int t  = bm + tl;
        if (c < CCH && t < TD)
            outT[(size_t)c * TD + t] = smf[c * 132 + tl] - sarr[c];   // CENTERED
    }
}

// ============================================================
// Kernel 1b: obs conv as Toeplitz bf16 GEMM (R14-verified)
// ============================================================
#define OB_BPW   212
#define OB_ZST   552
#define OB_ZW    276
#define OB_OFF_Z0 (OB_ZST)
#define OB_OFF_Z1 (OB_ZST + OB_ZW)
#define OB_OFF_B  (OB_ZST + 2 * OB_ZW)
#define OB_SMEM_WORDS (OB_OFF_B + 64 * OB_BPW)
#define OB_SMEM_BYTES (OB_SMEM_WORDS * 4)

__global__ __launch_bounds__(256) void obs_gemm_kernel(const float* __restrict__ Z)
{
    extern __shared__ float smf[];
    float*    zst = smf;
    uint32_t* zs0 = reinterpret_cast<uint32_t*>(smf + OB_OFF_Z0);
    uint32_t* zs1 = reinterpret_cast<uint32_t*>(smf + OB_OFF_Z1);
    uint32_t* Bs  = reinterpret_cast<uint32_t*>(smf + OB_OFF_B);

    const int tid = threadIdx.x;
    const int t0  = blockIdx.x * 128;

    for (int i = tid; i < OB_ZST; i += 256) {
        int t = t0 - TN + i;
        zst[i] = (t >= 0 && t < TD) ? Z[t] : 0.f;
    }
    for (int i = tid; i < 64 * OB_BPW; i += 256) Bs[i] = 0u;
    __syncthreads();

    for (int i = tid; i < OB_ZW; i += 256) {
        float a = zst[2 * i];
        float b = (2 * i + 1 < OB_ZST) ? zst[2 * i + 1] : 0.f;
        float c = (2 * i + 2 < OB_ZST) ? zst[2 * i + 2] : 0.f;
        zs0[i] = bf2(a, b);
        zs1[i] = bf2(b, c);
    }
    for (int i = tid; i < CCH * 201; i += 256) {
        int c = i / 201, w = i % 201;
        int e0 = 400 - 2 * w, e1 = 399 - 2 * w;
        float a = g_ok[c * (OBS_LEN + 3) + e0];
        float b = (e1 >= 0) ? g_ok[c * (OBS_LEN + 3) + e1] : 0.f;
        Bs[c * OB_BPW + w] = bf2(a, b);
    }
    __syncthreads();

    const int wid  = tid >> 5;
    const int lane = tid & 31;
    const int g    = lane >> 2;
    const int t4   = lane & 3;
    const int wm   = (wid & 3) * 32;
    const int wn   = (wid >> 2) * 32;
    const int par  = g & 1;
    const uint32_t* zb = par ? zs1 : zs0;

    float acc[2][4][4];
    #pragma unroll
    for (int mi = 0; mi < 2; mi++)
        #pragma unroll
        for (int ni = 0; ni < 4; ni++)
            #pragma unroll
            for (int r = 0; r < 4; r++) acc[mi][ni][r] = 0.f;

    int rb0 = (wm + g - par) >> 1;
    int rb1 = rb0 + 8;

    #pragma unroll 2
    for (int ks = 0; ks < 26; ks++) {
        const int kw = ks * 8;
        uint32_t af[2][4];
        af[0][0] = zb[rb0 + kw + t4];
        af[0][1] = zb[rb0 + 4 + kw + t4];
        af[0][2] = zb[rb0 + kw + 4 + t4];
        af[0][3] = zb[rb0 + 4 + kw + 4 + t4];
        af[1][0] = zb[rb1 + kw + t4];
        af[1][1] = zb[rb1 + 4 + kw + t4];
        af[1][2] = zb[rb1 + kw + 4 + t4];
        af[1][3] = zb[rb1 + 4 + kw + 4 + t4];
        uint32_t bf[4][2];
        #pragma unroll
        for (int ni = 0; ni < 4; ni++) {
            int n = wn + ni * 8 + g;
            bf[ni][0] = Bs[n * OB_BPW + kw + t4];
            bf[ni][1] = Bs[n * OB_BPW + kw + 4 + t4];
        }
        #pragma unroll
        for (int mi = 0; mi < 2; mi++)
            #pragma unroll
            for (int ni = 0; ni < 4; ni++) {
                asm volatile(
                    "mma.sync.aligned.m16n8k16.row.col.f32.bf16.bf16.f32 "
                    "{%0,%1,%2,%3}, {%4,%5,%6,%7}, {%8,%9}, {%0,%1,%2,%3};"
                    : "+f"(acc[mi][ni][0]), "+f"(acc[mi][ni][1]),
                      "+f"(acc[mi][ni][2]), "+f"(acc[mi][ni][3])
                    : "r"(af[mi][0]), "r"(af[mi][1]), "r"(af[mi][2]), "r"(af[mi][3]),
                      "r"(bf[ni][0]), "r"(bf[ni][1]));
            }
    }

    __syncthreads();
    #pragma unroll
    for (int mi = 0; mi < 2; mi++)
        #pragma unroll
        for (int ni = 0; ni < 4; ni++) {
            int n0 = wn + ni * 8 + 2 * t4;
            int m0 = wm + mi * 16 + g;
            smf[(n0)     * 132 + m0]     = acc[mi][ni][0];
            smf[(n0 + 1) * 132 + m0]     = acc[mi][ni][1];
            smf[(n0)     * 132 + m0 + 8] = acc[mi][ni][2];
            smf[(n0 + 1) * 132 + m0 + 8] = acc[mi][ni][3];
        }
    __syncthreads();
    for (int idx = tid; idx < 64 * 128; idx += 256) {
        int c  = idx >> 7;
        int tl = idx & 127;
        if (c < CCH)
            g_zf[(size_t)c * TDP + t0 + tl] = smf[c * 132 + tl];
    }
}

// ============================================================
// Kernel 1c: e/i conv as shift-batched Toeplitz bf16 GEMM
//   out[tt][n] = filt_e+filt_i at t = tbase + 32*tt + n
//   M=128 (time stride 32), N=32 shifts, K = 2 signals x 240
//   A: shared centered window, swizzle phys = i + (i>>3)
// ============================================================
#define EF_BPW    244                      // B row pitch (words)
#define EF_APHYS  2430                     // phys words per signal (2160 + 270)
#define EF_STAGE  4320                     // fp32 stage floats per signal
#define EF_OFF_A  0                        // words: A_e then A_i
#define EF_OFF_BST (2 * EF_APHYS)          // 4860: B (32*244=7808) / stage (2*4320=8640)
#define EF_OFF_K  (EF_OFF_BST + 2 * EF_STAGE)  // 13500: ek,ik fp32 (400)
#define EF_SMEM_WORDS (EF_OFF_K + 2 * TN + 4)  // 13904
#define EF_SMEM_BYTES (EF_SMEM_WORDS * 4)      // 55616

__global__ __launch_bounds__(256) void eif_gemm_kernel()
{
    extern __shared__ float smf[];
    uint32_t* Aw  = reinterpret_cast<uint32_t*>(smf + EF_OFF_A);
    float*    stg = smf + EF_OFF_BST;                          // stage (then B)
    uint32_t* Bs  = reinterpret_cast<uint32_t*>(smf + EF_OFF_BST);
    float*    ks_ = smf + EF_OFF_K;                            // ek[200] then ik[200]

    const int tid   = threadIdx.x;
    const int c     = blockIdx.x;
    const int tbase = blockIdx.y * EFTILE;

    const float s_e = g_se[c];
    const float s_i = g_si[c];

    // stage fp32 windows (centered; out-of-range = -s, representing zero-pad)
    const float* se_g = g_syn_e + (size_t)c * TD;
    const float* si_g = g_syn_i + (size_t)c * TD;
    for (int y = tid; y < EF_STAGE; y += 256) {
        int t = tbase - (TN - 1) - 32 + y + 31;                // = tbase - 199 + y... keep explicit below
        (void)t;
    }
    for (int y = tid; y < EF_STAGE; y += 256) {
        int t = tbase - 199 + y;
        stg[y]            = (t >= 0 && t < TD) ? se_g[t] : -s_e;
        stg[EF_STAGE + y] = (t >= 0 && t < TD) ? si_g[t] : -s_i;
    }
    for (int j = tid; j < TN; j += 256) {
        ks_[j]      = g_ek[c * TN + j];
        ks_[TN + j] = g_ik[c * TN + j];
    }
    __syncthreads();

    // A words (swizzled): logical i covers elems (2i, 2i+1)
    for (int i = tid; i < 2160; i += 256) {
        int ph = i + (i >> 3);
        Aw[ph]            = bf2(stg[2 * i],            stg[2 * i + 1]);
        Aw[EF_APHYS + ph] = bf2(stg[EF_STAGE + 2 * i], stg[EF_STAGE + 2 * i + 1]);
    }
    __syncthreads();

    // B words (overwrite stage): B[n][w] = (k[199+n-2w], k[198+n-2w])
    for (int idx = tid; idx < 32 * 120; idx += 256) {
        int n = idx / 120, w = idx % 120;
        int e0 = 199 + n - 2 * w;
        float lo_e = (e0 >= 0 && e0 < TN) ? ks_[e0] : 0.f;
        float hi_e = (e0 - 1 >= 0 && e0 - 1 < TN) ? ks_[e0 - 1] : 0.f;
        float lo_i = (e0 >= 0 && e0 < TN) ? ks_[TN + e0] : 0.f;
        float hi_i = (e0 - 1 >= 0 && e0 - 1 < TN) ? ks_[TN + e0 - 1] : 0.f;
        Bs[n * EF_BPW + w]       = bf2(lo_e, hi_e);
        Bs[n * EF_BPW + 120 + w] = bf2(lo_i, hi_i);
    }
    __syncthreads();

    const int wid  = tid >> 5;
    const int lane = tid & 31;
    const int g    = lane >> 2;
    const int t4   = lane & 3;
    const int wm   = (wid & 3) * 32;       // warp M offset (4 warps)
    const int wn   = (wid >> 2) * 16;      // warp N offset (2 warps x 16)

    float acc[2][2][4];
    #pragma unroll
    for (int mi = 0; mi < 2; mi++)
        #pragma unroll
        for (int ni = 0; ni < 2; ni++)
            #pragma unroll
            for (int r = 0; r < 4; r++) acc[mi][ni][r] = 0.f;

    #pragma unroll
    for (int sig = 0; sig < 2; sig++) {
        const uint32_t* Ab = Aw + sig * EF_APHYS;
        const int bofs = sig * 120;
        #pragma unroll 3
        for (int ks = 0; ks < 15; ks++) {
            const int kw = ks * 8;
            uint32_t af[2][4];
            #pragma unroll
            for (int mi = 0; mi < 2; mi++) {
                int r = wm + mi * 16 + g;
                int base = 18 * r + 9 * ks + t4;       // phys of word (16r + kw + t4)
                af[mi][0] = Ab[base];
                af[mi][1] = Ab[base + 144];            // row +8
                af[mi][2] = Ab[base + 4];
                af[mi][3] = Ab[base + 148];
            }
            uint32_t bf[2][2];
            #pragma unroll
            for (int ni = 0; ni < 2; ni++) {
                int n = wn + ni * 8 + g;
                bf[ni][0] = Bs[n * EF_BPW + bofs + kw + t4];
                bf[ni][1] = Bs[n * EF_BPW + bofs + kw + 4 + t4];
            }
            #pragma unroll
            for (int mi = 0; mi < 2; mi++)
                #pragma unroll
                for (int ni = 0; ni < 2; ni++) {
                    asm volatile(
                        "mma.sync.aligned.m16n8k16.row.col.f32.bf16.bf16.f32 "
                        "{%0,%1,%2,%3}, {%4,%5,%6,%7}, {%8,%9}, {%0,%1,%2,%3};"
                        : "+f"(acc[mi][ni][0]), "+f"(acc[mi][ni][1]),
                          "+f"(acc[mi][ni][2]), "+f"(acc[mi][ni][3])
                        : "r"(af[mi][0]), "r"(af[mi][1]), "r"(af[mi][2]), "r"(af[mi][3]),
                          "r"(bf[ni][0]), "r"(bf[ni][1]));
                }
        }
    }

    // epilogue: time offset within block = 32*row + col -> linear smem
    __syncthreads();
    #pragma unroll
    for (int mi = 0; mi < 2; mi++)
        #pragma unroll
        for (int ni = 0; ni < 2; ni++) {
            int n0 = wn + ni * 8 + 2 * t4;
            int m0 = wm + mi * 16 + g;
            smf[32 * m0 + n0]           = acc[mi][ni][0];
            smf[32 * m0 + n0 + 1]       = acc[mi][ni][1];
            smf[32 * (m0 + 8) + n0]     = acc[mi][ni][2];
            smf[32 * (m0 + 8) + n0 + 1] = acc[mi][ni][3];
        }
    __syncthreads();
    for (int i = tid; i < EFTILE; i += 256)
        g_ef[(size_t)c * EFP + tbase + i] = smf[i];
}

// ============================================================
// Kernel 2: final epilogue (ef + zf + corr -> Gumbel outputs)
// ============================================================
__global__ __launch_bounds__(256) void final_kernel(
    const float* __restrict__ u,
    const float* __restrict__ Theta,
    const float* __restrict__ temp_p,
    float* __restrict__ out)
{
    const int c   = blockIdx.x;
    const int t0  = blockIdx.y * TT;
    const int tid = threadIdx.x;
    const int tl0 = tid * 8;

    const float corr = g_corr[c];
    const float th   = Theta[c];
    const float temp = *temp_p;

    float acc[8];
    {
        const float4* ef = reinterpret_cast<const float4*>(&g_ef[(size_t)c * EFP + t0 + tl0]);
        const float4* zf = reinterpret_cast<const float4*>(&g_zf[(size_t)c * TDP + t0 + tl0]);
        float4 a = ef[0], b = ef[1], x = zf[0], y = zf[1];
        acc[0] = a.x + x.x; acc[1] = a.y + x.y; acc[2] = a.z + x.z; acc[3] = a.w + x.w;
        acc[4] = b.x + y.x; acc[5] = b.y + y.y; acc[6] = b.z + y.z; acc[7] = b.w + y.w;
    }

    #pragma unroll
    for (int i = 0; i < 8; i++) {
        int t = t0 + tl0 + i;
        if (t < TD) {
            float L0 = acc[i] + corr + th;
            float2 uv = *reinterpret_cast<const float2*>(&u[((size_t)t * CCH + c) * 2]);
            float g0 = -logf(-logf(uv.x + 1e-8f) + 1e-8f);
            float g1 = -logf(-logf(uv.y + 1e-8f) + 1e-8f);
            float zh = 1.f / (1.f + expf(-((L0 + g0 - g1) / temp)));
            float sg = 1.f / (1.f + expf(-L0));
            out[(size_t)t * CCH + c]                    = zh;
            out[(size_t)TD * CCH + (size_t)t * CCH + c] = sg;
        }
    }
}

// ============================================================
// launch
// ============================================================
extern "C" void kernel_launch(void* const* d_in, const int* in_sizes, int n_in,
                              void* d_out, int out_size)
{
    const float* S_e    = (const float*)d_in[0];
    const float* S_i    = (const float*)d_in[1];
    const float* Z_obs  = (const float*)d_in[2];
    const float* temp   = (const float*)d_in[3];
    const float* u      = (const float*)d_in[4];
    const float* C_se   = (const float*)d_in[5];
    const float* C_si   = (const float*)d_in[6];
    const float* W_syn  = (const float*)d_in[7];
    const float* W_obs  = (const float*)d_in[8];
    const float* Theta  = (const float*)d_in[9];
    float* out = (float*)d_out;
    (void)in_sizes; (void)n_in; (void)out_size;

    cudaFuncSetAttribute(gemm_bf16_kernel, cudaFuncAttributeMaxDynamicSharedMemorySize, GSMEM_BYTES);
    cudaFuncSetAttribute(obs_gemm_kernel,  cudaFuncAttributeMaxDynamicSharedMemorySize, OB_SMEM_BYTES);
    cudaFuncSetAttribute(eif_gemm_kernel,  cudaFuncAttributeMaxDynamicSharedMemorySize, EF_SMEM_BYTES);

    float* syn_e_ptr; float* syn_i_ptr;
    cudaGetSymbolAddress((void**)&syn_e_ptr, g_syn_e);
    cudaGetSymbolAddress((void**)&syn_i_ptr, g_syn_i);

    build_kernels_kernel<<<TN + OBS_LEN, 64>>>(W_syn, W_obs);
    aux_kernel<<<CCH, 256>>>(C_se, C_si);

    dim3 gg(GEMM_GX, 2);
    gemm_bf16_kernel<<<gg, 256, GSMEM_BYTES>>>(S_e, C_se, syn_e_ptr,
                                               S_i, C_si, syn_i_ptr);

    obs_gemm_kernel<<<GEMM_GX, 256, OB_SMEM_BYTES>>>(Z_obs);

    dim3 eg(CCH, EFNT);                    // 63 x 13
    eif_gemm_kernel<<<eg, 256, EF_SMEM_BYTES>>>();

    dim3 cg(CCH, NTILE);                   // 63 x 25
    final_kernel<<<cg, 256>>>(u, Theta, temp, out);
}

// round 16
// speedup vs baseline: 1.0695x; 1.0695x over previous
#include <cuda_runtime.h>
#include <cstdint>
#include <math.h>

// ---------------- problem constants ----------------
#define TD      50000
#define E_NO    2000
#define I_NO    500
#define CCH     63
#define TN      200
#define OBS_LEN 401
#define NB      13
#define PI_F    3.14159265358979323846f
#define TT      2048
#define NTILE   25
#define TDP     (NTILE * TT)               // 51200 padded stride

// ---------------- device scratch ----------------
__device__ float g_ek[CCH * TN];
__device__ float g_ik[CCH * TN];
__device__ float g_ok[CCH * (OBS_LEN + 3)];
__device__ float g_syn_e[CCH * TD];
__device__ float g_syn_i[CCH * TD];
__device__ float g_zf[CCH * TDP];          // obs result, padded

// pack two fp32 -> bf16x2 (lo = first, hi = second)
__device__ __forceinline__ uint32_t bf2(float lo, float hi) {
    uint32_t r;
    asm("cvt.rn.bf16x2.f32 %0, %1, %2;" : "=r"(r) : "f"(hi), "f"(lo));
    return r;
}

// ============================================================
// Kernel 0: build temporal kernels (601 blocks, fp32 MUFU basis)
// ============================================================
__global__ __launch_bounds__(64) void build_kernels_kernel(
    const float* __restrict__ W_syn,   // [63][13][2]
    const float* __restrict__ W_obs)   // [63][25]
{
    __shared__ float bs[NB];
    const int blk = blockIdx.x;
    const int tid = threadIdx.x;

    if (blk < TN) {
        const int j = blk;
        if (tid < NB) {
            float raw = 5.f * logf((float)j + 1.f + 1e-8f);
            float phi = 0.5f * PI_F * (float)tid;
            float v = 0.5f * cosf(raw - phi) + 0.5f;
            if (raw < phi - PI_F || raw > phi + PI_F) v = 0.f;
            bs[tid] = v;
        }
        __syncthreads();
        if (tid < CCH) {
            const int c = tid;
            float ae = 0.f, ai = 0.f;
            #pragma unroll
            for (int b = 0; b < NB; b++) {
                ae = fmaf(W_syn[(c * NB + b) * 2 + 0], bs[b], ae);
                ai = fmaf(W_syn[(c * NB + b) * 2 + 1], bs[b], ai);
            }
            g_ek[c * TN + j] = ae;
            g_ik[c * TN + j] = ai;
        }
    } else {
        const int j = blk - TN;            // 0..400
        if (tid < NB) {
            float xo = (float)(j - TN);
            float raw = 5.f * logf(fabsf(xo) + 1.f + 1e-8f);
            float phi = 0.5f * PI_F * (float)tid;
            float v = 0.5f * cosf(raw - phi) + 0.5f;
            if (raw < phi - PI_F || raw > phi + PI_F) v = 0.f;
            bs[tid] = v;
        }
        __syncthreads();
        if (tid < CCH) {
            const int c = tid;
            float a = W_obs[c * 25 + 0] * bs[0];
            #pragma unroll
            for (int b = 1; b < NB; b++) {
                if (j >= TN) a = fmaf(W_obs[c * 25 + 2 * b - 1], bs[b], a);
                if (j <= TN) a = fmaf(W_obs[c * 25 + 2 * b    ], bs[b], a);
            }
            g_ok[c * (OBS_LEN + 3) + j] = a;
        }
    }
}

// ============================================================
// Kernel 1: bf16 mma.sync GEMM (R8/R14-verified config)
// ============================================================
#define GBM     128
#define GBK     32
#define APW     20
#define AW      (128 * APW)
#define BW      (64 * APW)
#define STW     (AW + BW)
#define GSMEM_BYTES (64 * 132 * 4)         // 33792 B
#define GEMM_GX 391

__global__ __launch_bounds__(256) void gemm_bf16_kernel(
    const float* __restrict__ Ae, const float* __restrict__ Cse, float* __restrict__ oute,
    const float* __restrict__ Ai, const float* __restrict__ Csi, float* __restrict__ outi)
{
    extern __shared__ float smf[];
    uint32_t* smw = reinterpret_cast<uint32_t*>(smf);

    const float* A; const float* Cs; float* outT; int K;
    if (blockIdx.y == 0) { A = Ae; Cs = Cse; outT = oute; K = E_NO; }
    else                 { A = Ai; Cs = Csi; outT = outi; K = I_NO; }
    const int S = (K + GBK - 1) / GBK;

    const int tid  = threadIdx.x;
    const int wid  = tid >> 5;
    const int lane = tid & 31;
    const int g    = lane >> 2;
    const int t4   = lane & 3;
    const int wm   = (wid & 3) * 32;
    const int wn   = (wid >> 2) * 32;
    const int bm   = blockIdx.x * GBM;

    float acc[2][4][4];
    #pragma unroll
    for (int mi = 0; mi < 2; mi++)
        #pragma unroll
        for (int ni = 0; ni < 4; ni++)
            #pragma unroll
            for (int r = 0; r < 4; r++) acc[mi][ni][r] = 0.f;

    float4 ra[4], rb[2];

    auto ldg_stage = [&](int s) {
        const int k0 = s * GBK;
        #pragma unroll
        for (int j = 0; j < 4; j++) {
            int idx = tid + 256 * j, r = idx >> 3, q = idx & 7, k = k0 + q * 4;
            float4 v = make_float4(0.f, 0.f, 0.f, 0.f);
            if ((bm + r < TD) && (k + 4 <= K))
                v = *reinterpret_cast<const float4*>(A + (size_t)(bm + r) * K + k);
            ra[j] = v;
        }
        #pragma unroll
        for (int j = 0; j < 2; j++) {
            int idx = tid + 256 * j, r = idx >> 3, q = idx & 7, k = k0 + q * 4;
            float4 v = make_float4(0.f, 0.f, 0.f, 0.f);
            if ((r < CCH) && (k + 4 <= K))
                v = *reinterpret_cast<const float4*>(Cs + (size_t)(r + 1) * K + k);
            rb[j] = v;
        }
    };
    auto sts_stage = [&](int buf) {
        uint32_t* ab = smw + buf * STW;
        uint32_t* bb = ab + AW;
        #pragma unroll
        for (int j = 0; j < 4; j++) {
            int idx = tid + 256 * j, r = idx >> 3, q = idx & 7;
            uint2* p = reinterpret_cast<uint2*>(ab + r * APW + q * 2);
            *p = make_uint2(bf2(ra[j].x, ra[j].y), bf2(ra[j].z, ra[j].w));
        }
        #pragma unroll
        for (int j = 0; j < 2; j++) {
            int idx = tid + 256 * j, r = idx >> 3, q = idx & 7;
            uint2* p = reinterpret_cast<uint2*>(bb + r * APW + q * 2);
            *p = make_uint2(bf2(rb[j].x, rb[j].y), bf2(rb[j].z, rb[j].w));
        }
    };
    auto compute = [&](int buf) {
        const uint32_t* As = smw + buf * STW;
        const uint32_t* Bs = As + AW;
        #pragma unroll
        for (int ks = 0; ks < 2; ks++) {
            const int kw = ks * 8;
            uint32_t af[2][4];
            #pragma unroll
            for (int mi = 0; mi < 2; mi++) {
                int r = wm + mi * 16 + g;
                af[mi][0] = As[(r)     * APW + kw + t4];
                af[mi][1] = As[(r + 8) * APW + kw + t4];
                af[mi][2] = As[(r)     * APW + kw + 4 + t4];
                af[mi][3] = As[(r + 8) * APW + kw + 4 + t4];
            }
            uint32_t bf[4][2];
            #pragma unroll
            for (int ni = 0; ni < 4; ni++) {
                int n = wn + ni * 8 + g;
                bf[ni][0] = Bs[n * APW + kw + t4];
                bf[ni][1] = Bs[n * APW + kw + 4 + t4];
            }
            #pragma unroll
            for (int mi = 0; mi < 2; mi++)
                #pragma unroll
                for (int ni = 0; ni < 4; ni++) {
                    asm volatile(
                        "mma.sync.aligned.m16n8k16.row.col.f32.bf16.bf16.f32 "
                        "{%0,%1,%2,%3}, {%4,%5,%6,%7}, {%8,%9}, {%0,%1,%2,%3};"
                        : "+f"(acc[mi][ni][0]), "+f"(acc[mi][ni][1]),
                          "+f"(acc[mi][ni][2]), "+f"(acc[mi][ni][3])
                        : "r"(af[mi][0]), "r"(af[mi][1]), "r"(af[mi][2]), "r"(af[mi][3]),
                          "r"(bf[ni][0]), "r"(bf[ni][1]));
                }
        }
    };

    ldg_stage(0);
    sts_stage(0);
    __syncthreads();

    for (int s = 0; s < S; s++) {
        const bool have_next = (s + 1 < S);
        if (have_next) ldg_stage(s + 1);
        compute(s & 1);
        __syncthreads();
        if (have_next) {
            sts_stage((s + 1) & 1);
            __syncthreads();
        }
    }

    #pragma unroll
    for (int mi = 0; mi < 2; mi++)
        #pragma unroll
        for (int ni = 0; ni < 4; ni++) {
            int n0 = wn + ni * 8 + 2 * t4;
            int m0 = wm + mi * 16 + g;
            smf[(n0)     * 132 + m0]     = acc[mi][ni][0];
            smf[(n0 + 1) * 132 + m0]     = acc[mi][ni][1];
            smf[(n0)     * 132 + m0 + 8] = acc[mi][ni][2];
            smf[(n0 + 1) * 132 + m0 + 8] = acc[mi][ni][3];
        }
    __syncthreads();
    for (int idx = tid; idx < 64 * 128; idx += 256) {
        int c  = idx >> 7;
        int tl = idx & 127;
        int t  = bm + tl;
        if (c < CCH && t < TD)
            outT[(size_t)c * TD + t] = smf[c * 132 + tl];
    }
}

// ============================================================
// Kernel 1b: obs conv as Toeplitz bf16 GEMM (R14-verified)
// ============================================================
#define OB_BPW   212
#define OB_ZST   552
#define OB_ZW    276
#define OB_OFF_Z0 (OB_ZST)
#define OB_OFF_Z1 (OB_ZST + OB_ZW)
#define OB_OFF_B  (OB_ZST + 2 * OB_ZW)
#define OB_SMEM_WORDS (OB_OFF_B + 64 * OB_BPW)
#define OB_SMEM_BYTES (OB_SMEM_WORDS * 4)

__global__ __launch_bounds__(256) void obs_gemm_kernel(const float* __restrict__ Z)
{
    extern __shared__ float smf[];
    float*    zst = smf;
    uint32_t* zs0 = reinterpret_cast<uint32_t*>(smf + OB_OFF_Z0);
    uint32_t* zs1 = reinterpret_cast<uint32_t*>(smf + OB_OFF_Z1);
    uint32_t* Bs  = reinterpret_cast<uint32_t*>(smf + OB_OFF_B);

    const int tid = threadIdx.x;
    const int t0  = blockIdx.x * 128;

    for (int i = tid; i < OB_ZST; i += 256) {
        int t = t0 - TN + i;
        zst[i] = (t >= 0 && t < TD) ? Z[t] : 0.f;
    }
    for (int i = tid; i < 64 * OB_BPW; i += 256) Bs[i] = 0u;
    __syncthreads();

    for (int i = tid; i < OB_ZW; i += 256) {
        float a = zst[2 * i];
        float b = (2 * i + 1 < OB_ZST) ? zst[2 * i + 1] : 0.f;
        float c = (2 * i + 2 < OB_ZST) ? zst[2 * i + 2] : 0.f;
        zs0[i] = bf2(a, b);
        zs1[i] = bf2(b, c);
    }
    for (int i = tid; i < CCH * 201; i += 256) {
        int c = i / 201, w = i % 201;
        int e0 = 400 - 2 * w, e1 = 399 - 2 * w;
        float a = g_ok[c * (OBS_LEN + 3) + e0];
        float b = (e1 >= 0) ? g_ok[c * (OBS_LEN + 3) + e1] : 0.f;
        Bs[c * OB_BPW + w] = bf2(a, b);
    }
    __syncthreads();

    const int wid  = tid >> 5;
    const int lane = tid & 31;
    const int g    = lane >> 2;
    const int t4   = lane & 3;
    const int wm   = (wid & 3) * 32;
    const int wn   = (wid >> 2) * 32;
    const int par  = g & 1;
    const uint32_t* zb = par ? zs1 : zs0;

    float acc[2][4][4];
    #pragma unroll
    for (int mi = 0; mi < 2; mi++)
        #pragma unroll
        for (int ni = 0; ni < 4; ni++)
            #pragma unroll
            for (int r = 0; r < 4; r++) acc[mi][ni][r] = 0.f;

    int rb0 = (wm + g - par) >> 1;
    int rb1 = rb0 + 8;

    #pragma unroll 2
    for (int ks = 0; ks < 26; ks++) {
        const int kw = ks * 8;
        uint32_t af[2][4];
        af[0][0] = zb[rb0 + kw + t4];
        af[0][1] = zb[rb0 + 4 + kw + t4];
        af[0][2] = zb[rb0 + kw + 4 + t4];
        af[0][3] = zb[rb0 + 4 + kw + 4 + t4];
        af[1][0] = zb[rb1 + kw + t4];
        af[1][1] = zb[rb1 + 4 + kw + t4];
        af[1][2] = zb[rb1 + kw + 4 + t4];
        af[1][3] = zb[rb1 + 4 + kw + 4 + t4];
        uint32_t bf[4][2];
        #pragma unroll
        for (int ni = 0; ni < 4; ni++) {
            int n = wn + ni * 8 + g;
            bf[ni][0] = Bs[n * OB_BPW + kw + t4];
            bf[ni][1] = Bs[n * OB_BPW + kw + 4 + t4];
        }
        #pragma unroll
        for (int mi = 0; mi < 2; mi++)
            #pragma unroll
            for (int ni = 0; ni < 4; ni++) {
                asm volatile(
                    "mma.sync.aligned.m16n8k16.row.col.f32.bf16.bf16.f32 "
                    "{%0,%1,%2,%3}, {%4,%5,%6,%7}, {%8,%9}, {%0,%1,%2,%3};"
                    : "+f"(acc[mi][ni][0]), "+f"(acc[mi][ni][1]),
                      "+f"(acc[mi][ni][2]), "+f"(acc[mi][ni][3])
                    : "r"(af[mi][0]), "r"(af[mi][1]), "r"(af[mi][2]), "r"(af[mi][3]),
                      "r"(bf[ni][0]), "r"(bf[ni][1]));
            }
    }

    __syncthreads();
    #pragma unroll
    for (int mi = 0; mi < 2; mi++)
        #pragma unroll
        for (int ni = 0; ni < 4; ni++) {
            int n0 = wn + ni * 8 + 2 * t4;
            int m0 = wm + mi * 16 + g;
            smf[(n0)     * 132 + m0]     = acc[mi][ni][0];
            smf[(n0 + 1) * 132 + m0]     = acc[mi][ni][1];
            smf[(n0)     * 132 + m0 + 8] = acc[mi][ni][2];
            smf[(n0 + 1) * 132 + m0 + 8] = acc[mi][ni][3];
        }
    __syncthreads();
    for (int idx = tid; idx < 64 * 128; idx += 256) {
        int c  = idx >> 7;
        int tl = idx & 127;
        if (c < CCH)
            g_zf[(size_t)c * TDP + t0 + tl] = smf[c * 132 + tl];
    }
}

// ============================================================
// Kernel 2: e/i convs (sliding register window) + zf + fast epilogue
// ============================================================
__global__ __launch_bounds__(256) void conv_finish_kernel(
    const float* __restrict__ u,
    const float* __restrict__ Theta,
    const float* __restrict__ temp_p,
    float* __restrict__ out)
{
    __shared__ __align__(16) float se_s[TT + TN + 16];
    __shared__ __align__(16) float si_s[TT + TN + 16];
    __shared__ __align__(16) float ek_s[TN];
    __shared__ __align__(16) float ik_s[TN];

    const int c   = blockIdx.x;
    const int t0  = blockIdx.y * TT;
    const int tid = threadIdx.x;

    const float* se_g = g_syn_e + (size_t)c * TD;
    const float* si_g = g_syn_i + (size_t)c * TD;

    for (int i = tid; i < TT + TN + 16; i += 256) {
        int t = t0 - (TN - 1) + i;
        float ve = 0.f, vi = 0.f;
        if (t >= 0 && t < TD) { ve = se_g[t]; vi = si_g[t]; }
        se_s[i] = ve; si_s[i] = vi;
    }
    for (int j = tid; j < TN; j += 256) {
        ek_s[j] = g_ek[c * TN + j];
        ik_s[j] = g_ik[c * TN + j];
    }
    __syncthreads();

    const int tl0 = tid * 8;
    float acc[8];
    {
        const float4* zf = reinterpret_cast<const float4*>(&g_zf[(size_t)c * TDP + t0 + tl0]);
        float4 a = zf[0], b = zf[1];
        acc[0] = a.x; acc[1] = a.y; acc[2] = a.z; acc[3] = a.w;
        acc[4] = b.x; acc[5] = b.y; acc[6] = b.z; acc[7] = b.w;
    }

    {
        float ew[12], iw[12];
        #pragma unroll
        for (int x = 0; x < 3; x++) {
            float4 a = *reinterpret_cast<const float4*>(&se_s[tl0 + 4 * x]);
            float4 b = *reinterpret_cast<const float4*>(&si_s[tl0 + 4 * x]);
            ew[4 * x] = a.x; ew[4 * x + 1] = a.y; ew[4 * x + 2] = a.z; ew[4 * x + 3] = a.w;
            iw[4 * x] = b.x; iw[4 * x + 1] = b.y; iw[4 * x + 2] = b.z; iw[4 * x + 3] = b.w;
        }
        #pragma unroll 5
        for (int p = 0; p < 50; p++) {
            float4 we4 = *reinterpret_cast<const float4*>(&ek_s[196 - 4 * p]);
            float4 wi4 = *reinterpret_cast<const float4*>(&ik_s[196 - 4 * p]);
            float4 ne  = *reinterpret_cast<const float4*>(&se_s[tl0 + 12 + 4 * p]);
            float4 ni  = *reinterpret_cast<const float4*>(&si_s[tl0 + 12 + 4 * p]);
            const float we[4] = {we4.x, we4.y, we4.z, we4.w};
            const float wi[4] = {wi4.x, wi4.y, wi4.z, wi4.w};
            #pragma unroll
            for (int dj = 0; dj < 4; dj++) {
                #pragma unroll
                for (int i = 0; i < 8; i++) {
                    acc[i] = fmaf(ew[i + 3 - dj], we[dj], acc[i]);
                    acc[i] = fmaf(iw[i + 3 - dj], wi[dj], acc[i]);
                }
            }
            #pragma unroll
            for (int x = 0; x < 8; x++) { ew[x] = ew[x + 4]; iw[x] = iw[x + 4]; }
            ew[8] = ne.x; ew[9] = ne.y; ew[10] = ne.z; ew[11] = ne.w;
            iw[8] = ni.x; iw[9] = ni.y; iw[10] = ni.z; iw[11] = ni.w;
        }
    }

    // ---------- fast-math epilogue ----------
    // g0 - g1 = -log(a0) + log(a1) = log(a1/a0), a_k = -log(u_k+eps)+eps
    const float th   = Theta[c];
    const float invt = 1.f / (*temp_p);
    #pragma unroll
    for (int i = 0; i < 8; i++) {
        int t = t0 + tl0 + i;
        if (t < TD) {
            float L0 = acc[i] + th;
            float2 uv = *reinterpret_cast<const float2*>(&u[((size_t)t * CCH + c) * 2]);
            float a0 = -__logf(uv.x + 1e-8f) + 1e-8f;
            float a1 = -__logf(uv.y + 1e-8f) + 1e-8f;
            float d  = __logf(__fdividef(a1, a0));
            float zh = 1.f / (1.f + __expf(-(L0 + d) * invt));
            float sg = 1.f / (1.f + __expf(-L0));
            out[(size_t)t * CCH + c]                    = zh;
            out[(size_t)TD * CCH + (size_t)t * CCH + c] = sg;
        }
    }
}

// ============================================================
// launch
// ============================================================
extern "C" void kernel_launch(void* const* d_in, const int* in_sizes, int n_in,
                              void* d_out, int out_size)
{
    const float* S_e    = (const float*)d_in[0];
    const float* S_i    = (const float*)d_in[1];
    const float* Z_obs  = (const float*)d_in[2];
    const float* temp   = (const float*)d_in[3];
    const float* u      = (const float*)d_in[4];
    const float* C_se   = (const float*)d_in[5];
    const float* C_si   = (const float*)d_in[6];
    const float* W_syn  = (const float*)d_in[7];
    const float* W_obs  = (const float*)d_in[8];
    const float* Theta  = (const float*)d_in[9];
    float* out = (float*)d_out;
    (void)in_sizes; (void)n_in; (void)out_size;

    cudaFuncSetAttribute(gemm_bf16_kernel, cudaFuncAttributeMaxDynamicSharedMemorySize, GSMEM_BYTES);
    cudaFuncSetAttribute(obs_gemm_kernel,  cudaFuncAttributeMaxDynamicSharedMemorySize, OB_SMEM_BYTES);

    float* syn_e_ptr; float* syn_i_ptr;
    cudaGetSymbolAddress((void**)&syn_e_ptr, g_syn_e);
    cudaGetSymbolAddress((void**)&syn_i_ptr, g_syn_i);

    build_kernels_kernel<<<TN + OBS_LEN, 64>>>(W_syn, W_obs);

    dim3 gg(GEMM_GX, 2);
    gemm_bf16_kernel<<<gg, 256, GSMEM_BYTES>>>(S_e, C_se, syn_e_ptr,
                                               S_i, C_si, syn_i_ptr);

    obs_gemm_kernel<<<GEMM_GX, 256, OB_SMEM_BYTES>>>(Z_obs);

    dim3 cg(CCH, NTILE);
    conv_finish_kernel<<<cg, 256>>>(u, Theta, temp, out);
}